// round 3
// baseline (speedup 1.0000x reference)
#include <cuda_runtime.h>
#include <cstdint>

#define T_STEPS 300
#define BATCH   256
#define NIN     128
#define NH      512
#define NOUT    3

#define B_TILE   16
#define N_TILE   64
#define NB       (NH / N_TILE)      /* 8  */
#define BB       (BATCH / B_TILE)   /* 16 */
#define GRID_SZ  (NB * BB)          /* 128 */
#define NTHREADS 128

#define H_STRIDE  (NH + 4)
#define IN_STRIDE (NIN + 4)
#define SMEM_FLOATS (NH * N_TILE + NIN * N_TILE + B_TILE * H_STRIDE + B_TILE * IN_STRIDE)

// Cross-CTA activation buffer (double-buffered) + per-step barrier counters.
__device__ float        g_h[2][BATCH * NH];
__device__ unsigned int g_bar[T_STEPS];

__device__ __forceinline__ unsigned ld_acquire(const unsigned* p) {
    unsigned v;
    asm volatile("ld.acquire.gpu.global.u32 %0, [%1];" : "=r"(v) : "l"(p) : "memory");
    return v;
}
__device__ __forceinline__ unsigned atom_add_release(unsigned* p, unsigned v) {
    unsigned old;
    asm volatile("atom.release.gpu.global.add.u32 %0, [%1], %2;"
                 : "=r"(old) : "l"(p), "r"(v) : "memory");
    return old;
}

// acc[r][0..3] += h_r * w4  for both rows, one k slice
#define FMA_ROWS(hx_a, hx_b, wv)                                   \
    do {                                                           \
        acc[0][0] = fmaf((hx_a), (wv).x, acc[0][0]);               \
        acc[0][1] = fmaf((hx_a), (wv).y, acc[0][1]);               \
        acc[0][2] = fmaf((hx_a), (wv).z, acc[0][2]);               \
        acc[0][3] = fmaf((hx_a), (wv).w, acc[0][3]);               \
        acc[1][0] = fmaf((hx_b), (wv).x, acc[1][0]);               \
        acc[1][1] = fmaf((hx_b), (wv).y, acc[1][1]);               \
        acc[1][2] = fmaf((hx_b), (wv).z, acc[1][2]);               \
        acc[1][3] = fmaf((hx_b), (wv).w, acc[1][3]);               \
    } while (0)

__global__ void __launch_bounds__(NTHREADS, 1)
rnn_kernel(const float* __restrict__ input_data,  // [T,B,NIN]
           const float* __restrict__ noise,       // [T,B,NH]
           const float* __restrict__ x_init,      // [B,NH]
           const float* __restrict__ sx_init,     // [B,NH]
           const float* __restrict__ su_init,     // [B,NH]
           const float* __restrict__ w_in,        // [NIN,NH]
           const float* __restrict__ w_in_mask,   // [NIN,NH]
           const float* __restrict__ w_rnn_base,  // [NH,NH]
           const float* __restrict__ conn_mask,   // [NH,NH]
           const float* __restrict__ ei,          // [NH,NH] (diag)
           const float* __restrict__ b_rnn,       // [NH]
           const float* __restrict__ alpha_std,   // [NH]
           const float* __restrict__ alpha_stf,   // [NH]
           const float* __restrict__ Uv,          // [NH]
           const float* __restrict__ dynsyn,      // [NH]
           float* __restrict__ x_seq_out)         // [B,T,NH]
{
    extern __shared__ float smem[];
    float* w_s  = smem;                                   // [NH][N_TILE]   k-major
    float* wi_s = w_s  + NH * N_TILE;                     // [NIN][N_TILE]
    float* h_s  = wi_s + NIN * N_TILE;                    // [B_TILE][H_STRIDE]
    float* in_s = h_s  + B_TILE * H_STRIDE;               // [B_TILE][IN_STRIDE]

    const int cta = blockIdx.x;
    const int bi  = cta / NB;
    const int nj  = cta % NB;
    const int b0  = bi * B_TILE;
    const int n0  = nj * N_TILE;
    const int tid = threadIdx.x;
    const int cg  = tid & 15;           // column group: 4 cols
    const int rp  = tid >> 4;           // row pair: 0..7
    const int n   = n0 + (cg << 2);     // first of this thread's 4 columns
    const int br0 = b0 + (rp << 1);     // first of this thread's 2 batch rows

    // ---- one-time: build masked/EI-signed weight slices in shared ----
    for (int idx = tid; idx < NH * N_TILE; idx += NTHREADS) {
        int k = idx >> 6, c = idx & 63;
        float sgn = ei[(size_t)k * NH + k];
        float v   = w_rnn_base[(size_t)k * NH + n0 + c] * conn_mask[(size_t)k * NH + n0 + c];
        w_s[idx]  = sgn * fmaxf(v, 0.0f);
    }
    for (int idx = tid; idx < NIN * N_TILE; idx += NTHREADS) {
        int k = idx >> 6, c = idx & 63;
        wi_s[idx] = w_in[(size_t)k * NH + n0 + c] * w_in_mask[(size_t)k * NH + n0 + c];
    }

    // ---- per-thread constants and state (registers for all 300 steps) ----
    float ast[4], asf[4], uu[4], dyn[4], brn[4];
    *(float4*)ast = *(const float4*)(alpha_std + n);
    *(float4*)asf = *(const float4*)(alpha_stf + n);
    *(float4*)uu  = *(const float4*)(Uv + n);
    *(float4*)dyn = *(const float4*)(dynsyn + n);
    *(float4*)brn = *(const float4*)(b_rnn + n);

    float xv[2][4], sx[2][4], su[2][4];
#pragma unroll
    for (int r = 0; r < 2; ++r) {
        *(float4*)xv[r] = *(const float4*)(x_init  + (size_t)(br0 + r) * NH + n);
        *(float4*)sx[r] = *(const float4*)(sx_init + (size_t)(br0 + r) * NH + n);
        *(float4*)su[r] = *(const float4*)(su_init + (size_t)(br0 + r) * NH + n);
    }

    __syncthreads();

    for (int t = 0; t < T_STEPS; ++t) {
        // ---------- Phase A: STP update, publish h ----------
        float xp[2][4];
        float* hb = g_h[t & 1];
#pragma unroll
        for (int r = 0; r < 2; ++r) {
            float hv[4];
#pragma unroll
            for (int j = 0; j < 4; ++j) {
                float rr  = fmaxf(xv[r][j], 0.0f);
                float sxn = sx[r][j] + (ast[j] * (1.0f - sx[r][j]) - 0.01f * su[r][j] * sx[r][j] * rr) * dyn[j];
                float sun = su[r][j] + (asf[j] * (uu[j] - su[r][j]) + 0.01f * uu[j] * (1.0f - su[r][j]) * rr) * dyn[j];
                sxn = fminf(fmaxf(sxn, 0.0f), 1.0f);
                sun = fminf(fmaxf(sun, 0.0f), 1.0f);
                sx[r][j] = sxn; su[r][j] = sun;
                xp[r][j] = sun * sxn * xv[r][j];
                hv[j]    = fmaxf(xp[r][j], 0.0f);
            }
            __stcg((float4*)(hb + (size_t)(br0 + r) * NH + n), *(float4*)hv);
        }

        // ---------- arrive at barrier (no wait yet) ----------
        __syncthreads();                  // all h stores of this CTA issued
        if (tid == 0) {
            __threadfence();
            atom_add_release(&g_bar[t], 1u);
        }

        // ---------- overlapped with barrier: input GEMM (h-independent) ----------
        const float* inp_t = input_data + (size_t)t * BATCH * NIN;
        for (int idx = tid; idx < (B_TILE * NIN) / 4; idx += NTHREADS) {
            int row = idx >> 5, k4 = idx & 31;    // NIN/4 = 32
            float4 v = *(const float4*)(inp_t + (size_t)(b0 + row) * NIN + (k4 << 2));
            *(float4*)(in_s + row * IN_STRIDE + (k4 << 2)) = v;
        }
        __syncthreads();

        float acc[2][4];
#pragma unroll
        for (int j = 0; j < 4; ++j) { acc[0][j] = brn[j]; acc[1][j] = brn[j]; }

        {
            const float* irow0 = in_s + (rp << 1) * IN_STRIDE;
            const float* irow1 = irow0 + IN_STRIDE;
            const float* wic   = wi_s + (cg << 2);
#pragma unroll 4
            for (int k = 0; k < NIN; k += 4) {
                float4 ha = *(const float4*)(irow0 + k);
                float4 hbv = *(const float4*)(irow1 + k);
                float4 w0 = *(const float4*)(wic + (k + 0) * N_TILE);
                float4 w1 = *(const float4*)(wic + (k + 1) * N_TILE);
                float4 w2 = *(const float4*)(wic + (k + 2) * N_TILE);
                float4 w3 = *(const float4*)(wic + (k + 3) * N_TILE);
                FMA_ROWS(ha.x, hbv.x, w0);
                FMA_ROWS(ha.y, hbv.y, w1);
                FMA_ROWS(ha.z, hbv.z, w2);
                FMA_ROWS(ha.w, hbv.w, w3);
            }
        }

        // ---------- barrier wait ----------
        if (tid == 0) {
            if (ld_acquire(&g_bar[t]) < (unsigned)GRID_SZ) {
                while (ld_acquire(&g_bar[t]) < (unsigned)GRID_SZ) { __nanosleep(32); }
            }
        }
        __syncthreads();

        // ---------- stage h tile, recurrent GEMM ----------
        const float* hbr = g_h[t & 1];
        for (int idx = tid; idx < (B_TILE * NH) / 4; idx += NTHREADS) {
            int row = idx >> 7, k4 = idx & 127;   // NH/4 = 128
            float4 v = __ldcg((const float4*)(hbr + (size_t)(b0 + row) * NH + (k4 << 2)));
            *(float4*)(h_s + row * H_STRIDE + (k4 << 2)) = v;
        }
        __syncthreads();

        {
            const float* hrow0 = h_s + (rp << 1) * H_STRIDE;
            const float* hrow1 = hrow0 + H_STRIDE;
            const float* wc    = w_s + (cg << 2);
#pragma unroll 4
            for (int k = 0; k < NH; k += 4) {
                float4 ha = *(const float4*)(hrow0 + k);
                float4 hbv = *(const float4*)(hrow1 + k);
                float4 w0 = *(const float4*)(wc + (k + 0) * N_TILE);
                float4 w1 = *(const float4*)(wc + (k + 1) * N_TILE);
                float4 w2 = *(const float4*)(wc + (k + 2) * N_TILE);
                float4 w3 = *(const float4*)(wc + (k + 3) * N_TILE);
                FMA_ROWS(ha.x, hbv.x, w0);
                FMA_ROWS(ha.y, hbv.y, w1);
                FMA_ROWS(ha.z, hbv.z, w2);
                FMA_ROWS(ha.w, hbv.w, w3);
            }
        }

        // ---------- state update + x_seq store ----------
#pragma unroll
        for (int r = 0; r < 2; ++r) {
            float4 nz = *(const float4*)(noise + ((size_t)t * BATCH + (br0 + r)) * NH + n);
            float nza[4] = {nz.x, nz.y, nz.z, nz.w};
            float xn[4];
#pragma unroll
            for (int j = 0; j < 4; ++j) {
                xn[j]    = 0.8f * xp[r][j] + 0.2f * acc[r][j] + nza[j];
                xv[r][j] = xn[j];
            }
            *(float4*)(x_seq_out + ((size_t)(br0 + r) * T_STEPS + t) * NH + n) = *(float4*)xn;
        }
    }
}

// y = softmax_over_batch( relu(x_seq) @ relu(w_out*mask) + b_out )
__global__ void out_kernel(const float* __restrict__ w_out,
                           const float* __restrict__ w_out_mask,
                           const float* __restrict__ b_out,
                           const float* __restrict__ x_seq,   // [B,T,NH]
                           float* __restrict__ y_out)         // [B,T,NOUT]
{
    __shared__ float wo[NH * NOUT];
    __shared__ float red[256];
    const int t = blockIdx.x;
    const int b = threadIdx.x;    // 256 threads = batch

    for (int i = b; i < NH * NOUT; i += 256)
        wo[i] = fmaxf(w_out[i] * w_out_mask[i], 0.0f);
    __syncthreads();

    const float* xr = x_seq + ((size_t)b * T_STEPS + t) * NH;
    float a0 = 0.f, a1 = 0.f, a2 = 0.f;
#pragma unroll 4
    for (int k = 0; k < NH; k += 4) {
        float4 x4 = __ldg((const float4*)(xr + k));
        float r;
        r = fmaxf(x4.x, 0.f); a0 = fmaf(r, wo[(k+0)*3+0], a0); a1 = fmaf(r, wo[(k+0)*3+1], a1); a2 = fmaf(r, wo[(k+0)*3+2], a2);
        r = fmaxf(x4.y, 0.f); a0 = fmaf(r, wo[(k+1)*3+0], a0); a1 = fmaf(r, wo[(k+1)*3+1], a1); a2 = fmaf(r, wo[(k+1)*3+2], a2);
        r = fmaxf(x4.z, 0.f); a0 = fmaf(r, wo[(k+2)*3+0], a0); a1 = fmaf(r, wo[(k+2)*3+1], a1); a2 = fmaf(r, wo[(k+2)*3+2], a2);
        r = fmaxf(x4.w, 0.f); a0 = fmaf(r, wo[(k+3)*3+0], a0); a1 = fmaf(r, wo[(k+3)*3+1], a1); a2 = fmaf(r, wo[(k+3)*3+2], a2);
    }
    float y[3] = {a0 + b_out[0], a1 + b_out[1], a2 + b_out[2]};

#pragma unroll
    for (int c = 0; c < NOUT; ++c) {
        red[b] = y[c];
        __syncthreads();
        for (int s = 128; s > 0; s >>= 1) {
            if (b < s) red[b] = fmaxf(red[b], red[b + s]);
            __syncthreads();
        }
        float m = red[0];
        __syncthreads();
        float ev = expf(y[c] - m);
        red[b] = ev;
        __syncthreads();
        for (int s = 128; s > 0; s >>= 1) {
            if (b < s) red[b] += red[b + s];
            __syncthreads();
        }
        float ssum = red[0];
        __syncthreads();
        y_out[((size_t)b * T_STEPS + t) * NOUT + c] = ev / ssum;
    }
}

extern "C" void kernel_launch(void* const* d_in, const int* in_sizes, int n_in,
                              void* d_out, int out_size)
{
    const float* input_data = (const float*)d_in[0];
    const float* noise      = (const float*)d_in[1];
    const float* x_init     = (const float*)d_in[2];
    const float* sx_init    = (const float*)d_in[3];
    const float* su_init    = (const float*)d_in[4];
    const float* w_in       = (const float*)d_in[5];
    const float* w_in_mask  = (const float*)d_in[6];
    const float* w_rnn_base = (const float*)d_in[7];
    const float* conn_mask  = (const float*)d_in[8];
    const float* ei         = (const float*)d_in[9];
    const float* b_rnn      = (const float*)d_in[10];
    const float* w_out      = (const float*)d_in[11];
    const float* w_out_mask = (const float*)d_in[12];
    const float* b_out      = (const float*)d_in[13];
    const float* alpha_std  = (const float*)d_in[14];
    const float* alpha_stf  = (const float*)d_in[15];
    const float* Uv         = (const float*)d_in[16];
    const float* dynsyn     = (const float*)d_in[17];

    // Output layout: tuple (y_output [B,T,NOUT], x_seq [B,T,NH]) concatenated.
    float* y_out = (float*)d_out;
    float* x_seq = (float*)d_out + (size_t)BATCH * T_STEPS * NOUT;

    // Zero barrier counters each launch (graph-capturable memset node).
    void* barp = nullptr;
    cudaGetSymbolAddress(&barp, g_bar);
    cudaMemsetAsync(barp, 0, sizeof(unsigned) * T_STEPS);

    size_t smem = SMEM_FLOATS * sizeof(float);   // ~205 KB
    cudaFuncSetAttribute(rnn_kernel, cudaFuncAttributeMaxDynamicSharedMemorySize, (int)smem);

    rnn_kernel<<<GRID_SZ, NTHREADS, smem>>>(
        input_data, noise, x_init, sx_init, su_init,
        w_in, w_in_mask, w_rnn_base, conn_mask, ei, b_rnn,
        alpha_std, alpha_stf, Uv, dynsyn, x_seq);

    out_kernel<<<T_STEPS, 256>>>(w_out, w_out_mask, b_out, x_seq, y_out);
}